// round 12
// baseline (speedup 1.0000x reference)
#include <cuda_runtime.h>
#include <cstdint>

// SpanRepresentation: out[b, span, :] = concat(x[b, start], x[b, end], width_emb[w-1])
//   x: (16, 512, 768) f32, width_emb: (8, 64) f32, L = 512
//   spans: width w=1..8, start s=0..L-w  -> 4068 spans
//   out: (16, 4068, 1600) f32
//
// R11: one more step on the span-packing lever (only lever that keeps
// winning: 1->2 spans -1.5%, 2->4 -1.2%). Now 8 spans per 512-thread CTA:
// each 128-thread quad copies 2 consecutive spans (12.8KB contiguous per
// quad, 51.2KB per CTA). Grid 509x16 with tail guard (4068 % 8 = 4).

namespace {

constexpr int B  = 16;
constexpr int L  = 512;
constexpr int D  = 768;
constexpr int WD = 64;

// cumulative span offsets per width index wi (0-based): off[wi] = wi*L - wi*(wi-1)/2
constexpr int OFF1 = 1 * L - 0;            // 512
constexpr int OFF2 = 2 * L - 1;            // 1023
constexpr int OFF3 = 3 * L - 3;            // 1533
constexpr int OFF4 = 4 * L - 6;            // 2042
constexpr int OFF5 = 5 * L - 10;           // 2550
constexpr int OFF6 = 6 * L - 15;           // 3057
constexpr int OFF7 = 7 * L - 21;           // 3563
constexpr int NSPANS = 8 * L - 28;         // 4068

constexpr int D4    = D / 4;               // 192 float4 per x row
constexpr int WD4   = WD / 4;              // 16 float4 per width_emb row
constexpr int ROW4  = 2 * D4 + WD4;        // 400 float4 per output row (6400 B)

constexpr int THREADS = 512;               // four 128-thread quads
constexpr int SPANS_PER_CTA = 8;           // 2 consecutive spans per quad

} // namespace

__device__ __forceinline__ void copy_row(const float4* __restrict__ x,
                                         const float4* __restrict__ wemb,
                                         float4* __restrict__ out,
                                         int b, int span, int t)
{
    // width index via 7 compares against constexpr cumulative offsets
    int wi = 0;
    if (span >= OFF1) wi = 1;
    if (span >= OFF2) wi = 2;
    if (span >= OFF3) wi = 3;
    if (span >= OFF4) wi = 4;
    if (span >= OFF5) wi = 5;
    if (span >= OFF6) wi = 6;
    if (span >= OFF7) wi = 7;

    int off;
    switch (wi) {
        case 0: off = 0;    break;
        case 1: off = OFF1; break;
        case 2: off = OFF2; break;
        case 3: off = OFF3; break;
        case 4: off = OFF4; break;
        case 5: off = OFF5; break;
        case 6: off = OFF6; break;
        default: off = OFF7; break;
    }
    const int s = span - off;          // start position
    const int e = s + wi;              // end position (= s + w - 1)

    const float4* __restrict__ xs = x + (size_t)(b * L + s) * D4;
    const float4* __restrict__ xe = x + (size_t)(b * L + e) * D4;
    const float4* __restrict__ we = wemb + wi * WD4;
    float4* __restrict__ o = out + (size_t)(b * NSPANS + span) * (size_t)ROW4;

    // 400 float4 per row; 128 threads -> 4 strided passes (last partial)
    #pragma unroll
    for (int j = 0; j < 4; ++j) {
        const int idx = t + j * 128;
        if (idx < D4) {
            __stcs(o + idx, __ldg(xs + idx));
        } else if (idx < 2 * D4) {
            __stcs(o + idx, __ldg(xe + (idx - D4)));
        } else if (idx < ROW4) {
            __stcs(o + idx, __ldg(we + (idx - 2 * D4)));
        }
    }
}

__global__ __launch_bounds__(THREADS, 4)
void span_repr_kernel(const float4* __restrict__ x,
                      const float4* __restrict__ wemb,
                      float4* __restrict__ out)
{
    const int quad = threadIdx.x >> 7;            // 0..3 (warp-aligned split)
    const int t    = threadIdx.x & 127;           // lane within the quad
    const int b    = blockIdx.y;                  // 0..B-1

    // quad q handles 2 consecutive spans -> 12.8KB contiguous output per quad
    const int span0 = blockIdx.x * SPANS_PER_CTA + quad * 2;

    if (span0 < NSPANS)     copy_row(x, wemb, out, b, span0,     t);
    if (span0 + 1 < NSPANS) copy_row(x, wemb, out, b, span0 + 1, t);
}

extern "C" void kernel_launch(void* const* d_in, const int* in_sizes, int n_in,
                              void* d_out, int out_size)
{
    const float4* x    = (const float4*)d_in[0];   // (16, 512, 768) f32
    const float4* wemb = (const float4*)d_in[1];   // (8, 64) f32
    // d_in[2] = batch_max_seq_len (== 512, fixed for this instance) — unused
    float4* out = (float4*)d_out;

    dim3 grid((NSPANS + SPANS_PER_CTA - 1) / SPANS_PER_CTA, B);   // 509 x 16
    span_repr_kernel<<<grid, THREADS>>>(x, wemb, out);
}

// round 13
// speedup vs baseline: 1.0107x; 1.0107x over previous
#include <cuda_runtime.h>
#include <cstdint>

// SpanRepresentation: out[b, span, :] = concat(x[b, start], x[b, end], width_emb[w-1])
//   x: (16, 512, 768) f32, width_emb: (8, 64) f32, L = 512
//   spans: width w=1..8, start s=0..L-w  -> 4068 spans
//   out: (16, 4068, 1600) f32
//
// R12: R9 config (best: 4 spans per 512-thread CTA, one span per
// 128-thread quad) with the ONE untested knob flipped: default write-back
// stores instead of __stcs streaming stores. Lets L2 absorb/coalesce the
// 417MB write-once stream before writeback (better DRAM page locality at
// the MC) instead of forcing evict-first at CTA granularity.

namespace {

constexpr int B  = 16;
constexpr int L  = 512;
constexpr int D  = 768;
constexpr int WD = 64;

// cumulative span offsets per width index wi (0-based): off[wi] = wi*L - wi*(wi-1)/2
constexpr int OFF1 = 1 * L - 0;            // 512
constexpr int OFF2 = 2 * L - 1;            // 1023
constexpr int OFF3 = 3 * L - 3;            // 1533
constexpr int OFF4 = 4 * L - 6;            // 2042
constexpr int OFF5 = 5 * L - 10;           // 2550
constexpr int OFF6 = 6 * L - 15;           // 3057
constexpr int OFF7 = 7 * L - 21;           // 3563
constexpr int NSPANS = 8 * L - 28;         // 4068 (divisible by 4)

constexpr int D4    = D / 4;               // 192 float4 per x row
constexpr int WD4   = WD / 4;              // 16 float4 per width_emb row
constexpr int ROW4  = 2 * D4 + WD4;        // 400 float4 per output row (6400 B)

constexpr int THREADS = 512;               // four 128-thread quads, one span each
constexpr int SPANS_PER_CTA = 4;

} // namespace

__global__ __launch_bounds__(THREADS, 4)
void span_repr_kernel(const float4* __restrict__ x,
                      const float4* __restrict__ wemb,
                      float4* __restrict__ out)
{
    const int quad = threadIdx.x >> 7;            // 0..3 (warp-aligned split)
    const int t    = threadIdx.x & 127;           // lane within the quad
    const int span = blockIdx.x * SPANS_PER_CTA + quad;  // 0..NSPANS-1
    const int b    = blockIdx.y;                  // 0..B-1

    // width index via 7 compares against constexpr cumulative offsets
    int wi = 0;
    if (span >= OFF1) wi = 1;
    if (span >= OFF2) wi = 2;
    if (span >= OFF3) wi = 3;
    if (span >= OFF4) wi = 4;
    if (span >= OFF5) wi = 5;
    if (span >= OFF6) wi = 6;
    if (span >= OFF7) wi = 7;

    int off;
    switch (wi) {
        case 0: off = 0;    break;
        case 1: off = OFF1; break;
        case 2: off = OFF2; break;
        case 3: off = OFF3; break;
        case 4: off = OFF4; break;
        case 5: off = OFF5; break;
        case 6: off = OFF6; break;
        default: off = OFF7; break;
    }
    const int s = span - off;          // start position
    const int e = s + wi;              // end position (= s + w - 1)

    const float4* __restrict__ xs = x + (size_t)(b * L + s) * D4;
    const float4* __restrict__ xe = x + (size_t)(b * L + e) * D4;
    const float4* __restrict__ we = wemb + wi * WD4;
    float4* __restrict__ o = out + (size_t)(b * NSPANS + span) * (size_t)ROW4;

    // 400 float4 per row; 128 threads per quad -> 4 strided passes (last partial)
    #pragma unroll
    for (int j = 0; j < 4; ++j) {
        const int idx = t + j * 128;
        if (idx < D4) {
            o[idx] = __ldg(xs + idx);
        } else if (idx < 2 * D4) {
            o[idx] = __ldg(xe + (idx - D4));
        } else if (idx < ROW4) {
            o[idx] = __ldg(we + (idx - 2 * D4));
        }
    }
}

extern "C" void kernel_launch(void* const* d_in, const int* in_sizes, int n_in,
                              void* d_out, int out_size)
{
    const float4* x    = (const float4*)d_in[0];   // (16, 512, 768) f32
    const float4* wemb = (const float4*)d_in[1];   // (8, 64) f32
    // d_in[2] = batch_max_seq_len (== 512, fixed for this instance) — unused
    float4* out = (float4*)d_out;

    dim3 grid(NSPANS / SPANS_PER_CTA, B);   // 1017 x 16
    span_repr_kernel<<<grid, THREADS>>>(x, wemb, out);
}

// round 15
// speedup vs baseline: 1.0227x; 1.0118x over previous
#include <cuda_runtime.h>
#include <cstdint>

// SpanRepresentation: out[b, span, :] = concat(x[b, start], x[b, end], width_emb[w-1])
//   x: (16, 512, 768) f32, width_emb: (8, 64) f32, L = 512
//   spans: width w=1..8, start s=0..L-w  -> 4068 spans
//   out: (16, 4068, 1600) f32
//
// FINAL (= R9, measured best: 64.0us wall / 63.5us ncu, DRAM 75.9%,
// 6017 GB/s HBM). Converged configuration after 9 benched variants:
//   - 4 consecutive spans per 512-thread CTA, one span per 128-thread quad
//     (packing curve peaks here: 1->2 -1.5%, 2->4 -1.2%, 4->8 +3.6%)
//   - float4 LDG (L2-resident x reuse) + __stcs evict-first streaming STG
//     (write-back stores regressed +2.5%: output stream thrashes x in L2)
//   - branchless constexpr width decode (no div/mod)
//   - TMA bulk-store variants regressed (+3%, +7%): sync/occupancy cost
//     exceeds the L1tex store-path saving at this CTA granularity.
// All register-path variants pin DRAM at ~74-76% active — the empirical
// GB300@NAT ceiling for a 417MB write-dominated stream.

namespace {

constexpr int B  = 16;
constexpr int L  = 512;
constexpr int D  = 768;
constexpr int WD = 64;

// cumulative span offsets per width index wi (0-based): off[wi] = wi*L - wi*(wi-1)/2
constexpr int OFF1 = 1 * L - 0;            // 512
constexpr int OFF2 = 2 * L - 1;            // 1023
constexpr int OFF3 = 3 * L - 3;            // 1533
constexpr int OFF4 = 4 * L - 6;            // 2042
constexpr int OFF5 = 5 * L - 10;           // 2550
constexpr int OFF6 = 6 * L - 15;           // 3057
constexpr int OFF7 = 7 * L - 21;           // 3563
constexpr int NSPANS = 8 * L - 28;         // 4068 (divisible by 4)

constexpr int D4    = D / 4;               // 192 float4 per x row
constexpr int WD4   = WD / 4;              // 16 float4 per width_emb row
constexpr int ROW4  = 2 * D4 + WD4;        // 400 float4 per output row (6400 B)

constexpr int THREADS = 512;               // four 128-thread quads, one span each
constexpr int SPANS_PER_CTA = 4;

} // namespace

__global__ __launch_bounds__(THREADS, 4)
void span_repr_kernel(const float4* __restrict__ x,
                      const float4* __restrict__ wemb,
                      float4* __restrict__ out)
{
    const int quad = threadIdx.x >> 7;            // 0..3 (warp-aligned split)
    const int t    = threadIdx.x & 127;           // lane within the quad
    const int span = blockIdx.x * SPANS_PER_CTA + quad;  // 0..NSPANS-1
    const int b    = blockIdx.y;                  // 0..B-1

    // width index via 7 compares against constexpr cumulative offsets
    int wi = 0;
    if (span >= OFF1) wi = 1;
    if (span >= OFF2) wi = 2;
    if (span >= OFF3) wi = 3;
    if (span >= OFF4) wi = 4;
    if (span >= OFF5) wi = 5;
    if (span >= OFF6) wi = 6;
    if (span >= OFF7) wi = 7;

    int off;
    switch (wi) {
        case 0: off = 0;    break;
        case 1: off = OFF1; break;
        case 2: off = OFF2; break;
        case 3: off = OFF3; break;
        case 4: off = OFF4; break;
        case 5: off = OFF5; break;
        case 6: off = OFF6; break;
        default: off = OFF7; break;
    }
    const int s = span - off;          // start position
    const int e = s + wi;              // end position (= s + w - 1)

    const float4* __restrict__ xs = x + (size_t)(b * L + s) * D4;
    const float4* __restrict__ xe = x + (size_t)(b * L + e) * D4;
    const float4* __restrict__ we = wemb + wi * WD4;
    float4* __restrict__ o = out + (size_t)(b * NSPANS + span) * (size_t)ROW4;

    // 400 float4 per row; 128 threads per quad -> 4 strided passes (last partial)
    #pragma unroll
    for (int j = 0; j < 4; ++j) {
        const int idx = t + j * 128;
        if (idx < D4) {
            __stcs(o + idx, __ldg(xs + idx));
        } else if (idx < 2 * D4) {
            __stcs(o + idx, __ldg(xe + (idx - D4)));
        } else if (idx < ROW4) {
            __stcs(o + idx, __ldg(we + (idx - 2 * D4)));
        }
    }
}

extern "C" void kernel_launch(void* const* d_in, const int* in_sizes, int n_in,
                              void* d_out, int out_size)
{
    const float4* x    = (const float4*)d_in[0];   // (16, 512, 768) f32
    const float4* wemb = (const float4*)d_in[1];   // (8, 64) f32
    // d_in[2] = batch_max_seq_len (== 512, fixed for this instance) — unused
    float4* out = (float4*)d_out;

    dim3 grid(NSPANS / SPANS_PER_CTA, B);   // 1017 x 16
    span_repr_kernel<<<grid, THREADS>>>(x, wemb, out);
}